// round 8
// baseline (speedup 1.0000x reference)
#include <cuda_runtime.h>
#include <cuda_bf16.h>
#include <math.h>
#include <stdint.h>

// ---------------- problem constants ----------------
#define BATCH   16384
#define N_IN    128
#define CTX     128
#define HDIM    1024
#define NB      8
#define OUT_MULT 23                  // 3*NB - 1
#define N_OUT   (N_IN * OUT_MULT)    // 2944 = 23 * 128 exactly
#define N_OUT_P 3072                 // obuf row padding
#define KCAT    (CTX + N_IN)         // 256
#define TAIL    3.0f
#define MIN_W   0.001f
#define MIN_H   0.001f
#define MIN_D   0.001f
#define RQS_SCALE 724.07734393502f   // sqrt(1024*1024/2)

// int8 packed rows: 2 bytes per real element, 32-byte block per 16 real k.
// A-side: bytes[32q+i]    = q8(al * 8192)   (al = a - bf16(a))
//         bytes[32q+16+i] = q8(a * 16)
// B-side: bytes[32q+i]    = q8(bh * SBMUL)
//         bytes[32q+16+i] = q8(bl * 512 * SBMUL)
// One m16n8k32 s8 IMMA accumulates (al*bh + a*bl) * 8192*SBMUL.

// ---------------- scratch ----------------
__device__ __nv_bfloat16 g_xcat_hi[(size_t)BATCH * KCAT];
__device__ int8_t        g_xcat_i8[(size_t)BATCH * KCAT * 2];
__device__ __nv_bfloat16 g_wcat_hi[(size_t)HDIM * KCAT];
__device__ int8_t        g_wcat_i8[(size_t)HDIM * KCAT * 2];
__device__ __nv_bfloat16 g_w1_hi[(size_t)HDIM * HDIM];
__device__ int8_t        g_w1_i8[(size_t)HDIM * HDIM * 2];
__device__ __nv_bfloat16 g_w2_hi[(size_t)N_OUT * HDIM];
__device__ int8_t        g_w2_i8[(size_t)N_OUT * HDIM * 2];
__device__ __nv_bfloat16 g_h0_hi[(size_t)BATCH * HDIM];
__device__ int8_t        g_h0_i8[(size_t)BATCH * HDIM * 2];
__device__ __nv_bfloat16 g_h1_hi[(size_t)BATCH * HDIM];
__device__ int8_t        g_h1_i8[(size_t)BATCH * HDIM * 2];
__device__ float         g_out[(size_t)BATCH * N_OUT_P];
__device__ float         g_b0p[HDIM];
__device__ float         g_b1p[HDIM];

// ---------------- degree-sorted hidden permutation (analytic) ----------------
__host__ __device__ __forceinline__ int sorted_res(int j) {
    return (j < 72) ? (j / 9) : (8 + (j - 72) / 8);
}
__host__ __device__ __forceinline__ int sorted_orig(int j) {
    int r, c;
    if (j < 72) { r = j / 9; c = j % 9; }
    else        { int u = j - 72; r = 8 + u / 8; c = u % 8; }
    return c * 127 + r;
}

// ---------------- baseline-PTX helpers (compute_103-safe) ----------------
__device__ __forceinline__ uint32_t smem_to_u32(const void* p) {
    uint32_t a;
    asm("{ .reg .u64 t; cvta.to.shared.u64 t, %1; cvt.u32.u64 %0, t; }" : "=r"(a) : "l"(p));
    return a;
}

#define CP_ASYNC16(saddr, gptr) \
    asm volatile("cp.async.cg.shared.global [%0], [%1], 16;" :: "r"(saddr), "l"(gptr) : "memory")
#define CP_COMMIT()   asm volatile("cp.async.commit_group;" ::: "memory")
#define CP_WAIT(n)    asm volatile("cp.async.wait_group %0;" :: "n"(n) : "memory")

#define LDSM4(R, addr) \
    asm volatile("ldmatrix.sync.aligned.m8n8.x4.shared.b16 {%0,%1,%2,%3}, [%4];" \
        : "=r"((R)[0]), "=r"((R)[1]), "=r"((R)[2]), "=r"((R)[3]) : "r"(addr))

#define MMA_BF16(C, A, B0, B1) \
    asm volatile("mma.sync.aligned.m16n8k16.row.col.f32.bf16.bf16.f32 " \
        "{%0,%1,%2,%3}, {%4,%5,%6,%7}, {%8,%9}, {%0,%1,%2,%3};" \
        : "+f"((C)[0]), "+f"((C)[1]), "+f"((C)[2]), "+f"((C)[3]) \
        : "r"((A)[0]), "r"((A)[1]), "r"((A)[2]), "r"((A)[3]), "r"(B0), "r"(B1))

#define MMA_S8(C, A, B0, B1) \
    asm volatile("mma.sync.aligned.m16n8k32.row.col.s32.s8.s8.s32 " \
        "{%0,%1,%2,%3}, {%4,%5,%6,%7}, {%8,%9}, {%0,%1,%2,%3};" \
        : "+r"((C)[0]), "+r"((C)[1]), "+r"((C)[2]), "+r"((C)[3]) \
        : "r"((A)[0]), "r"((A)[1]), "r"((A)[2]), "r"((A)[3]), "r"(B0), "r"(B1))

__device__ __forceinline__ int8_t q8(float v) {
    int q = __float2int_rn(v);
    q = q > 127 ? 127 : (q < -127 ? -127 : q);
    return (int8_t)q;
}

// ---------------- prep kernels ----------------
__device__ __forceinline__ void write_a_elem(float v, __nv_bfloat16* hi, size_t hidx,
                                             int8_t* i8, size_t i8row, int c) {
    __nv_bfloat16 h = __float2bfloat16_rn(v);
    float al = v - __bfloat162float(h);
    hi[hidx] = h;
    size_t base = i8row + 32 * (c >> 4) + (c & 15);
    i8[base]      = q8(al * 8192.0f);
    i8[base + 16] = q8(v * 16.0f);
}
__device__ __forceinline__ void write_b_elem(float v, __nv_bfloat16* hi, size_t hidx,
                                             int8_t* i8, size_t i8row, int c, float sbmul) {
    __nv_bfloat16 h = __float2bfloat16_rn(v);
    float bh = __bfloat162float(h);
    hi[hidx] = h;
    size_t base = i8row + 32 * (c >> 4) + (c & 15);
    i8[base]      = q8(bh * sbmul);
    i8[base + 16] = q8((v - bh) * 512.0f * sbmul);
}

__global__ void k_prep_xcat(const float* __restrict__ x, const float* __restrict__ ctx,
                            __nv_bfloat16* __restrict__ hi, int8_t* __restrict__ i8) {
    int idx = blockIdx.x * blockDim.x + threadIdx.x;
    if (idx >= BATCH * KCAT) return;
    int b = idx >> 8, c = idx & 255;
    float v = (c < CTX) ? ctx[b * CTX + c] : x[b * N_IN + (c - CTX)];
    write_a_elem(v, hi, idx, i8, (size_t)b * 2 * KCAT, c);
}

__global__ void k_prep_wcat(const float* __restrict__ ctxw, const float* __restrict__ w0,
                            __nv_bfloat16* __restrict__ hi, int8_t* __restrict__ i8) {
    int idx = blockIdx.x * blockDim.x + threadIdx.x;
    if (idx >= HDIM * KCAT) return;
    int j = idx >> 8, c = idx & 255;
    int h = sorted_orig(j), r = sorted_res(j);
    float v;
    if (c < CTX) v = ctxw[h * CTX + c];
    else { int i = c - CTX; v = (r >= i) ? w0[h * N_IN + i] : 0.0f; }
    write_b_elem(v, hi, idx, i8, (size_t)j * 2 * KCAT, c, 128.0f);   // layer-1 sigma larger
}

__global__ void k_prep_w1(const float* __restrict__ w1,
                          __nv_bfloat16* __restrict__ hi, int8_t* __restrict__ i8) {
    int idx = blockIdx.x * blockDim.x + threadIdx.x;
    if (idx >= HDIM * HDIM) return;
    int j = idx >> 10, j2 = idx & 1023;
    float v = (sorted_res(j) >= sorted_res(j2))
            ? w1[(size_t)sorted_orig(j) * HDIM + sorted_orig(j2)] : 0.0f;
    write_b_elem(v, hi, idx, i8, (size_t)j * 2 * HDIM, j2, 256.0f);
}

__global__ void k_prep_w2(const float* __restrict__ w2,
                          __nv_bfloat16* __restrict__ hi, int8_t* __restrict__ i8) {
    int idx = blockIdx.x * blockDim.x + threadIdx.x;
    if (idx >= N_OUT * HDIM) return;
    int o = idx >> 10, j = idx & 1023;
    float v = ((o / OUT_MULT) > sorted_res(j)) ? w2[(size_t)o * HDIM + sorted_orig(j)] : 0.0f;
    write_b_elem(v, hi, idx, i8, (size_t)o * 2 * HDIM, j, 256.0f);
}

__global__ void k_prep_bias(const float* __restrict__ b0, const float* __restrict__ b1,
                            float* __restrict__ b0p, float* __restrict__ b1p) {
    int j = blockIdx.x * blockDim.x + threadIdx.x;
    if (j >= HDIM) return;
    int h = sorted_orig(j);
    b0p[j] = b0[h];
    b1p[j] = b1[h];
}

// ---------------- mixed bf16+int8 GEMM, triangular K-skip, 3-stage ----------
#define ST_AHI 0
#define ST_AI8 16384
#define ST_BHI 32768
#define ST_BI8 49152
#define STAGE_SZ 65536
#define NSTAGE 3
#define GSMEM (NSTAGE * STAGE_SZ + 1024)

__global__ __launch_bounds__(256, 1)
void gemm_mma(const __nv_bfloat16* __restrict__ Ahi, const int8_t* __restrict__ Ai8,
              const __nv_bfloat16* __restrict__ Bhi, const int8_t* __restrict__ Bi8,
              const float* __restrict__ bias, int K, int nvalid, int mode, float cscale,
              __nv_bfloat16* __restrict__ Chi, int8_t* __restrict__ Ci8,
              float* __restrict__ Cf, int ldc) {
    extern __shared__ char smem[];
    const uint32_t sb = smem_to_u32(smem);
    float* bias_s = (float*)(smem + NSTAGE * STAGE_SZ);

    const int tid = threadIdx.x;
    const int lane = tid & 31, wid = tid >> 5;
    const int gm = blockIdx.y * 128;
    // Descending-K launch order: largest-work N tiles first (better tail waves).
    const int gn = (gridDim.x - 1 - blockIdx.x) * 128;

    if (tid < 128) bias_s[tid] = (gn + tid < nvalid) ? bias[gn + tid] : 0.0f;

    // per-CTA effective K from the mask structure
    int keff = K;
    if (mode == 0) {
        int r = sorted_res(gn + 127);
        keff = CTX + r + 1;
    } else if (mode == 1) {
        int rp = sorted_res(gn + 127) + 1;
        keff = 8 * rp + min(rp, 8);
    } else if (mode == 2) {
        int q = min(gn + 127, N_OUT - 1) / OUT_MULT;
        keff = 8 * q + min(q, 8);
    }
    keff = min(K, (keff + 63) & ~63);

    int r_[4], c_[4]; uint32_t soff_[4];
#pragma unroll
    for (int i = 0; i < 4; i++) {
        int u = i * 256 + tid;
        r_[i] = u >> 3; c_[i] = u & 7;
        soff_[i] = (uint32_t)(r_[i] * 128 + ((c_[i] ^ (r_[i] & 7)) << 4));
    }

    const int wm = (wid & 3) * 32;
    const int nb = (wid >> 2) * 64;
    const int lr = lane & 7;
    const int gA = (lane >> 3) & 1;
    const int cpartA = (lane >> 4) & 1;
    const int kpB = (lane >> 3) & 1;
    const uint32_t xorv = (uint32_t)lr << 4;
    const uint32_t pA  = (uint32_t)((wm + gA * 8 + lr) * 128);
    const uint32_t pB4 = (uint32_t)((nb + ((lane >> 4) & 1) * 8 + lr) * 128);

    float acc[2][8][4];   // bf16 hi*hi
    int   icc[2][8][4];   // int8 cross, scaled by 8192*SBMUL/512 relative
#pragma unroll
    for (int t = 0; t < 2; t++)
#pragma unroll
        for (int j = 0; j < 8; j++)
#pragma unroll
            for (int q = 0; q < 4; q++) { acc[t][j][q] = 0.0f; icc[t][j][q] = 0; }

    const int nch = keff >> 6;

    auto load_stage = [&](int s, int k0) {
        uint32_t base = sb + (uint32_t)s * STAGE_SZ;
#pragma unroll
        for (int i = 0; i < 4; i++) {
            size_t ga16 = (size_t)(gm + r_[i]) * K + k0 + c_[i] * 8;
            size_t gb16 = (size_t)(gn + r_[i]) * K + k0 + c_[i] * 8;
            size_t gai8 = (size_t)(gm + r_[i]) * 2 * K + 2 * k0 + c_[i] * 16;
            size_t gbi8 = (size_t)(gn + r_[i]) * 2 * K + 2 * k0 + c_[i] * 16;
            CP_ASYNC16(base + ST_AHI + soff_[i], Ahi + ga16);
            CP_ASYNC16(base + ST_AI8 + soff_[i], Ai8 + gai8);
            CP_ASYNC16(base + ST_BHI + soff_[i], Bhi + gb16);
            CP_ASYNC16(base + ST_BI8 + soff_[i], Bi8 + gbi8);
        }
    };

    load_stage(0, 0);
    CP_COMMIT();
    if (nch > 1) { load_stage(1, 64); CP_COMMIT(); }

    for (int c = 0; c < nch; c++) {
        if (c + 1 < nch) CP_WAIT(1); else CP_WAIT(0);
        __syncthreads();

        if (c + 2 < nch) { load_stage((c + 2) % NSTAGE, (c + 2) << 6); CP_COMMIT(); }

        const uint32_t sA = sb + (uint32_t)(c % NSTAGE) * STAGE_SZ;
#pragma unroll
        for (int ks = 0; ks < 4; ks++) {
            const uint32_t offA = (uint32_t)(((ks * 2 + cpartA) << 4)) ^ xorv;
            const uint32_t offB = (uint32_t)(((ks * 2 + kpB) << 4)) ^ xorv;
            uint32_t ah0[4], ah1[4], ai0[4], ai1[4];
            LDSM4(ah0, sA + ST_AHI + pA + offA);
            LDSM4(ah1, sA + ST_AHI + pA + 2048 + offA);
            LDSM4(ai0, sA + ST_AI8 + pA + offA);
            LDSM4(ai1, sA + ST_AI8 + pA + 2048 + offA);
#pragma unroll
            for (int jp = 0; jp < 4; jp++) {
                uint32_t bh4[4], bi4[4];
                const uint32_t boff = pB4 + (uint32_t)(jp * 2048) + offB;
                LDSM4(bh4, sA + ST_BHI + boff);
                LDSM4(bi4, sA + ST_BI8 + boff);
                const int j0 = jp * 2, j1 = jp * 2 + 1;
                MMA_BF16(acc[0][j0], ah0, bh4[0], bh4[1]);
                MMA_BF16(acc[1][j0], ah1, bh4[0], bh4[1]);
                MMA_BF16(acc[0][j1], ah0, bh4[2], bh4[3]);
                MMA_BF16(acc[1][j1], ah1, bh4[2], bh4[3]);
                MMA_S8(icc[0][j0], ai0, bi4[0], bi4[1]);
                MMA_S8(icc[1][j0], ai1, bi4[0], bi4[1]);
                MMA_S8(icc[0][j1], ai0, bi4[2], bi4[3]);
                MMA_S8(icc[1][j1], ai1, bi4[2], bi4[3]);
            }
        }
    }

    // ---------------- epilogue ----------------
    const int qrow = lane >> 2;
    const int qcol = 2 * (lane & 3);
#pragma unroll
    for (int t = 0; t < 2; t++) {
#pragma unroll
        for (int j = 0; j < 8; j++) {
            const int colL = nb + j * 8 + qcol;
            const float b0 = bias_s[colL], b1 = bias_s[colL + 1];
#pragma unroll
            for (int h = 0; h < 2; h++) {
                const int row = gm + wm + t * 16 + h * 8 + qrow;
                float v0 = acc[t][j][h * 2 + 0] + (float)icc[t][j][h * 2 + 0] * cscale + b0;
                float v1 = acc[t][j][h * 2 + 1] + (float)icc[t][j][h * 2 + 1] * cscale + b1;
                if (Cf) {
                    *(float2*)(Cf + (size_t)row * ldc + gn + colL) = make_float2(v0, v1);
                } else {
                    v0 = fmaxf(v0, 0.0f); v1 = fmaxf(v1, 0.0f);
                    __nv_bfloat16 h0 = __float2bfloat16_rn(v0);
                    __nv_bfloat16 h1 = __float2bfloat16_rn(v1);
                    float f0 = __bfloat162float(h0), f1 = __bfloat162float(h1);
                    uint32_t wh = (uint32_t)__bfloat16_as_ushort(h0) | ((uint32_t)__bfloat16_as_ushort(h1) << 16);
                    *(uint32_t*)(Chi + (size_t)row * ldc + gn + colL) = wh;
                    // A-side int8 packing for the next layer
                    int gc = gn + colL;
                    size_t base = (size_t)row * 2 * ldc + 32 * (gc >> 4) + (gc & 15);
                    uint16_t lo = (uint16_t)(uint8_t)q8((v0 - f0) * 8192.0f)
                                | ((uint16_t)(uint8_t)q8((v1 - f1) * 8192.0f) << 8);
                    uint16_t fu = (uint16_t)(uint8_t)q8(v0 * 16.0f)
                                | ((uint16_t)(uint8_t)q8(v1 * 16.0f) << 8);
                    *(uint16_t*)(Ci8 + base)      = lo;
                    *(uint16_t*)(Ci8 + base + 16) = fu;
                }
            }
        }
    }
}

// ---------------- RQS spline + logdet reduction ----------------
__device__ __forceinline__ float softplusf(float v) {
    return (v > 20.0f) ? v : log1pf(expf(v));
}

__global__ void k_spline(const float* __restrict__ x, const float* __restrict__ out,
                         float* __restrict__ y_out, float* __restrict__ ld_out) {
    const int b = blockIdx.x;
    const int i = threadIdx.x;

    __shared__ float srow[N_OUT];
    const float4* orow = (const float4*)(out + (size_t)b * N_OUT_P);
#pragma unroll
    for (int u = i; u < N_OUT / 4; u += N_IN) ((float4*)srow)[u] = orow[u];
    __syncthreads();

    const float* o = srow + i * OUT_MULT;
    const float xi = x[(size_t)b * N_IN + i];

    float uw[NB], uh[NB];
#pragma unroll
    for (int j = 0; j < NB; j++) {
        uw[j] = o[j]      * (1.0f / RQS_SCALE);
        uh[j] = o[NB + j] * (1.0f / RQS_SCALE);
    }
    float mw = uw[0], mh = uh[0];
#pragma unroll
    for (int j = 1; j < NB; j++) { mw = fmaxf(mw, uw[j]); mh = fmaxf(mh, uh[j]); }
    float ew[NB], eh[NB], sw = 0.0f, sh = 0.0f;
#pragma unroll
    for (int j = 0; j < NB; j++) {
        ew[j] = expf(uw[j] - mw); sw += ew[j];
        eh[j] = expf(uh[j] - mh); sh += eh[j];
    }
    const float rw = (1.0f - MIN_W * NB) / sw;
    const float rh = (1.0f - MIN_H * NB) / sh;

    float cw[NB + 1], ch[NB + 1];
    cw[0] = -TAIL; ch[0] = -TAIL;
    float accw = 0.0f, acch = 0.0f;
#pragma unroll
    for (int j = 0; j < NB; j++) {
        accw += MIN_W + rw * ew[j];
        acch += MIN_H + rh * eh[j];
        cw[j + 1] = 2.0f * TAIL * accw - TAIL;
        ch[j + 1] = 2.0f * TAIL * acch - TAIL;
    }
    cw[NB] = TAIL; ch[NB] = TAIL;

    float d[NB + 1];
    d[0] = 1.0f; d[NB] = 1.0f;
#pragma unroll
    for (int j = 1; j < NB; j++) d[j] = MIN_D + softplusf(o[2 * NB + j - 1]);

    const float xc = fminf(fmaxf(xi, -TAIL), TAIL);
    int idx = 0;
#pragma unroll
    for (int k = 1; k <= NB; k++) idx += (xc >= cw[k]) ? 1 : 0;
    idx = min(idx, NB - 1);

    const float in_cw = cw[idx];
    const float in_w  = cw[idx + 1] - cw[idx];
    const float in_ch = ch[idx];
    const float in_h  = ch[idx + 1] - ch[idx];
    const float delta = in_h / in_w;
    const float d0 = d[idx], d1 = d[idx + 1];

    const float theta = (xc - in_cw) / in_w;
    const float t1m   = theta * (1.0f - theta);
    const float denom = delta + (d0 + d1 - 2.0f * delta) * t1m;
    const float num   = in_h * (delta * theta * theta + d0 * t1m);
    float y  = in_ch + num / denom;
    float ld = 2.0f * logf(delta)
             + logf(d1 * theta * theta + 2.0f * delta * t1m + d0 * (1.0f - theta) * (1.0f - theta))
             - 2.0f * logf(denom);

    const bool inside = fabsf(xi) <= TAIL;
    y_out[(size_t)b * N_IN + i] = inside ? y : xi;
    float ldv = inside ? ld : 0.0f;

    __shared__ float warp_sums[4];
#pragma unroll
    for (int off = 16; off > 0; off >>= 1)
        ldv += __shfl_down_sync(0xFFFFFFFFu, ldv, off);
    if ((i & 31) == 0) warp_sums[i >> 5] = ldv;
    __syncthreads();
    if (i == 0)
        ld_out[b] = warp_sums[0] + warp_sums[1] + warp_sums[2] + warp_sums[3];
}

// ---------------- launch ----------------
extern "C" void kernel_launch(void* const* d_in, const int* in_sizes, int n_in,
                              void* d_out, int out_size) {
    const float* x      = (const float*)d_in[0];
    const float* context= (const float*)d_in[1];
    const float* ctx_w  = (const float*)d_in[2];
    const float* w0     = (const float*)d_in[3];
    const float* b0     = (const float*)d_in[4];
    const float* w1     = (const float*)d_in[5];
    const float* b1     = (const float*)d_in[6];
    const float* w2     = (const float*)d_in[7];
    const float* b2     = (const float*)d_in[8];

    __nv_bfloat16 *xch, *wch, *w1h, *w2h, *h0h, *h1h;
    int8_t *xci, *wci, *w1i, *w2i, *h0i, *h1i;
    float *obuf, *b0p, *b1p;
    cudaGetSymbolAddress((void**)&xch, g_xcat_hi); cudaGetSymbolAddress((void**)&xci, g_xcat_i8);
    cudaGetSymbolAddress((void**)&wch, g_wcat_hi); cudaGetSymbolAddress((void**)&wci, g_wcat_i8);
    cudaGetSymbolAddress((void**)&w1h, g_w1_hi);   cudaGetSymbolAddress((void**)&w1i, g_w1_i8);
    cudaGetSymbolAddress((void**)&w2h, g_w2_hi);   cudaGetSymbolAddress((void**)&w2i, g_w2_i8);
    cudaGetSymbolAddress((void**)&h0h, g_h0_hi);   cudaGetSymbolAddress((void**)&h0i, g_h0_i8);
    cudaGetSymbolAddress((void**)&h1h, g_h1_hi);   cudaGetSymbolAddress((void**)&h1i, g_h1_i8);
    cudaGetSymbolAddress((void**)&obuf, g_out);
    cudaGetSymbolAddress((void**)&b0p, g_b0p);
    cudaGetSymbolAddress((void**)&b1p, g_b1p);

    cudaFuncSetAttribute(gemm_mma, cudaFuncAttributeMaxDynamicSharedMemorySize, GSMEM);

    const int TPB = 256;
    k_prep_xcat<<<(BATCH * KCAT + TPB - 1) / TPB, TPB>>>(x, context, xch, xci);
    k_prep_wcat<<<(HDIM * KCAT + TPB - 1) / TPB, TPB>>>(ctx_w, w0, wch, wci);
    k_prep_w1 <<<(HDIM * HDIM + TPB - 1) / TPB, TPB>>>(w1, w1h, w1i);
    k_prep_w2 <<<(N_OUT * HDIM + TPB - 1) / TPB, TPB>>>(w2, w2h, w2i);
    k_prep_bias<<<(HDIM + TPB - 1) / TPB, TPB>>>(b0, b1, b0p, b1p);

    // cross-term scales: s_a*s_b/512 with s_a=2^-4; s_b=2^-7 (L1), 2^-8 (L2/L3)
    const float CS1 = 1.0f / 1048576.0f;   // 2^-20
    const float CS2 = 1.0f / 2097152.0f;   // 2^-21

    // layer 1: triangular x-half (mode 0)
    gemm_mma<<<dim3(HDIM / 128, BATCH / 128), 256, GSMEM>>>(
        xch, xci, wch, wci, b0p, KCAT, HDIM, 0, CS1, h0h, h0i, nullptr, HDIM);
    // layer 2: sorted->sorted triangular (mode 1)
    gemm_mma<<<dim3(HDIM / 128, BATCH / 128), 256, GSMEM>>>(
        h0h, h0i, w1h, w1i, b1p, HDIM, HDIM, 1, CS2, h1h, h1i, nullptr, HDIM);
    // layer 3: natural rows vs sorted cols (mode 2)
    gemm_mma<<<dim3(N_OUT / 128, BATCH / 128), 256, GSMEM>>>(
        h1h, h1i, w2h, w2i, b2, HDIM, N_OUT, 2, CS2, nullptr, nullptr, obuf, N_OUT_P);

    float* yout = (float*)d_out;
    float* ldout = (float*)d_out + (size_t)BATCH * N_IN;
    k_spline<<<BATCH, N_IN>>>(x, obuf, yout, ldout);
}

// round 9
// speedup vs baseline: 3.0858x; 3.0858x over previous
#include <cuda_runtime.h>
#include <cuda_fp16.h>
#include <math.h>
#include <stdint.h>

// ---------------- problem constants ----------------
#define BATCH   16384
#define N_IN    128
#define CTX     128
#define HDIM    1024
#define NB      8
#define OUT_MULT 23                  // 3*NB - 1
#define N_OUT   (N_IN * OUT_MULT)    // 2944 = 23 * 128 exactly
#define N_OUT_P 3072                 // obuf row padding
#define KCAT    (CTX + N_IN)         // 256
#define TAIL    3.0f
#define MIN_W   0.001f
#define MIN_H   0.001f
#define MIN_D   0.001f
#define RQS_SCALE 724.07734393502f   // sqrt(1024*1024/2)

// Scheme: C = A_f16 @ (Bh + Bl)^T.  B split: bh = f16(b), bl = f16(b - bh).
// Only error: (a - f16(a))·b ~ 2^-13 RMS relative per layer.

// ---------------- scratch ----------------
__device__ __half g_xcat[(size_t)BATCH * KCAT];
__device__ __half g_wcat_hi[(size_t)HDIM * KCAT];
__device__ __half g_wcat_lo[(size_t)HDIM * KCAT];
__device__ __half g_w1_hi[(size_t)HDIM * HDIM];
__device__ __half g_w1_lo[(size_t)HDIM * HDIM];
__device__ __half g_w2_hi[(size_t)N_OUT * HDIM];
__device__ __half g_w2_lo[(size_t)N_OUT * HDIM];
__device__ __half g_h0[(size_t)BATCH * HDIM];
__device__ __half g_h1[(size_t)BATCH * HDIM];
__device__ float  g_out[(size_t)BATCH * N_OUT_P];
__device__ float  g_b0p[HDIM];
__device__ float  g_b1p[HDIM];

// ---------------- degree-sorted hidden permutation (analytic) ----------------
__host__ __device__ __forceinline__ int sorted_res(int j) {
    return (j < 72) ? (j / 9) : (8 + (j - 72) / 8);
}
__host__ __device__ __forceinline__ int sorted_orig(int j) {
    int r, c;
    if (j < 72) { r = j / 9; c = j % 9; }
    else        { int u = j - 72; r = 8 + u / 8; c = u % 8; }
    return c * 127 + r;
}

// ---------------- baseline-PTX helpers (compute_103-safe) ----------------
__device__ __forceinline__ uint32_t smem_to_u32(const void* p) {
    uint32_t a;
    asm("{ .reg .u64 t; cvta.to.shared.u64 t, %1; cvt.u32.u64 %0, t; }" : "=r"(a) : "l"(p));
    return a;
}

#define CP_ASYNC16(saddr, gptr) \
    asm volatile("cp.async.cg.shared.global [%0], [%1], 16;" :: "r"(saddr), "l"(gptr) : "memory")
#define CP_COMMIT()   asm volatile("cp.async.commit_group;" ::: "memory")
#define CP_WAIT(n)    asm volatile("cp.async.wait_group %0;" :: "n"(n) : "memory")

#define LDSM4(R, addr) \
    asm volatile("ldmatrix.sync.aligned.m8n8.x4.shared.b16 {%0,%1,%2,%3}, [%4];" \
        : "=r"((R)[0]), "=r"((R)[1]), "=r"((R)[2]), "=r"((R)[3]) : "r"(addr))

#define MMA_F16(C, A, B0, B1) \
    asm volatile("mma.sync.aligned.m16n8k16.row.col.f32.f16.f16.f32 " \
        "{%0,%1,%2,%3}, {%4,%5,%6,%7}, {%8,%9}, {%0,%1,%2,%3};" \
        : "+f"((C)[0]), "+f"((C)[1]), "+f"((C)[2]), "+f"((C)[3]) \
        : "r"((A)[0]), "r"((A)[1]), "r"((A)[2]), "r"((A)[3]), "r"(B0), "r"(B1))

// ---------------- prep kernels ----------------
__global__ void k_prep_xcat(const float* __restrict__ x, const float* __restrict__ ctx,
                            __half* __restrict__ a) {
    int idx = blockIdx.x * blockDim.x + threadIdx.x;
    if (idx >= BATCH * KCAT) return;
    int b = idx >> 8, c = idx & 255;
    float v = (c < CTX) ? ctx[b * CTX + c] : x[b * N_IN + (c - CTX)];
    a[idx] = __float2half_rn(v);
}

__device__ __forceinline__ void split_f16(float v, __half& h, __half& l) {
    h = __float2half_rn(v);
    l = __float2half_rn(v - __half2float(h));
}

__global__ void k_prep_wcat(const float* __restrict__ ctxw, const float* __restrict__ w0,
                            __half* __restrict__ hi, __half* __restrict__ lo) {
    int idx = blockIdx.x * blockDim.x + threadIdx.x;
    if (idx >= HDIM * KCAT) return;
    int j = idx >> 8, c = idx & 255;
    int h = sorted_orig(j), r = sorted_res(j);
    float v;
    if (c < CTX) v = ctxw[h * CTX + c];
    else { int i = c - CTX; v = (r >= i) ? w0[h * N_IN + i] : 0.0f; }
    split_f16(v, hi[idx], lo[idx]);
}

__global__ void k_prep_w1(const float* __restrict__ w1,
                          __half* __restrict__ hi, __half* __restrict__ lo) {
    int idx = blockIdx.x * blockDim.x + threadIdx.x;
    if (idx >= HDIM * HDIM) return;
    int j = idx >> 10, j2 = idx & 1023;
    float v = (sorted_res(j) >= sorted_res(j2))
            ? w1[(size_t)sorted_orig(j) * HDIM + sorted_orig(j2)] : 0.0f;
    split_f16(v, hi[idx], lo[idx]);
}

__global__ void k_prep_w2(const float* __restrict__ w2,
                          __half* __restrict__ hi, __half* __restrict__ lo) {
    int idx = blockIdx.x * blockDim.x + threadIdx.x;
    if (idx >= N_OUT * HDIM) return;
    int o = idx >> 10, j = idx & 1023;
    float v = ((o / OUT_MULT) > sorted_res(j)) ? w2[(size_t)o * HDIM + sorted_orig(j)] : 0.0f;
    split_f16(v, hi[idx], lo[idx]);
}

__global__ void k_prep_bias(const float* __restrict__ b0, const float* __restrict__ b1,
                            float* __restrict__ b0p, float* __restrict__ b1p) {
    int j = blockIdx.x * blockDim.x + threadIdx.x;
    if (j >= HDIM) return;
    int h = sorted_orig(j);
    b0p[j] = b0[h];
    b1p[j] = b1[h];
}

// ---------------- fp16 B-split GEMM, triangular K-skip, 3-stage ------------
#define ST_A  0
#define ST_BH 16384
#define ST_BL 32768
#define STAGE_SZ 49152
#define NSTAGE 3
#define GSMEM (NSTAGE * STAGE_SZ + 1024)

__global__ __launch_bounds__(256, 1)
void gemm_mma(const __half* __restrict__ A,
              const __half* __restrict__ Bhi, const __half* __restrict__ Blo,
              const float* __restrict__ bias, int K, int nvalid, int mode,
              __half* __restrict__ Ch, float* __restrict__ Cf, int ldc) {
    extern __shared__ char smem[];
    const uint32_t sb = smem_to_u32(smem);
    float* bias_s = (float*)(smem + NSTAGE * STAGE_SZ);

    const int tid = threadIdx.x;
    const int lane = tid & 31, wid = tid >> 5;
    const int gm = blockIdx.y * 128;
    // Descending-K launch order: largest-work N tiles first.
    const int gn = (gridDim.x - 1 - blockIdx.x) * 128;

    if (tid < 128) bias_s[tid] = (gn + tid < nvalid) ? bias[gn + tid] : 0.0f;

    // per-CTA effective K from the mask structure
    int keff = K;
    if (mode == 0) {
        int r = sorted_res(gn + 127);
        keff = CTX + r + 1;
    } else if (mode == 1) {
        int rp = sorted_res(gn + 127) + 1;
        keff = 8 * rp + min(rp, 8);
    } else if (mode == 2) {
        int q = min(gn + 127, N_OUT - 1) / OUT_MULT;
        keff = 8 * q + min(q, 8);
    }
    keff = min(K, (keff + 63) & ~63);

    int r_[4], c_[4]; uint32_t soff_[4];
#pragma unroll
    for (int i = 0; i < 4; i++) {
        int u = i * 256 + tid;
        r_[i] = u >> 3; c_[i] = u & 7;
        soff_[i] = (uint32_t)(r_[i] * 128 + ((c_[i] ^ (r_[i] & 7)) << 4));
    }

    const int wm = (wid & 3) * 32;
    const int nb = (wid >> 2) * 64;
    const int lr = lane & 7;
    const int gA = (lane >> 3) & 1;
    const int cpartA = (lane >> 4) & 1;
    const int kpB = (lane >> 3) & 1;
    const uint32_t xorv = (uint32_t)lr << 4;
    const uint32_t pA  = (uint32_t)((wm + gA * 8 + lr) * 128);
    const uint32_t pB4 = (uint32_t)((nb + ((lane >> 4) & 1) * 8 + lr) * 128);

    float acc[2][8][4];
#pragma unroll
    for (int t = 0; t < 2; t++)
#pragma unroll
        for (int j = 0; j < 8; j++)
#pragma unroll
            for (int q = 0; q < 4; q++) acc[t][j][q] = 0.0f;

    const int nch = keff >> 6;

    auto load_stage = [&](int s, int k0) {
        uint32_t base = sb + (uint32_t)s * STAGE_SZ;
#pragma unroll
        for (int i = 0; i < 4; i++) {
            size_t ga = (size_t)(gm + r_[i]) * K + k0 + c_[i] * 8;
            size_t gb = (size_t)(gn + r_[i]) * K + k0 + c_[i] * 8;
            CP_ASYNC16(base + ST_A  + soff_[i], A   + ga);
            CP_ASYNC16(base + ST_BH + soff_[i], Bhi + gb);
            CP_ASYNC16(base + ST_BL + soff_[i], Blo + gb);
        }
    };

    load_stage(0, 0);
    CP_COMMIT();
    if (nch > 1) { load_stage(1, 64); CP_COMMIT(); }

    for (int c = 0; c < nch; c++) {
        // stages 0..min(c+1, nch-1) committed; need stage c -> allow 1 pending.
        if (c + 1 < nch) CP_WAIT(1); else CP_WAIT(0);
        __syncthreads();

        if (c + 2 < nch) { load_stage((c + 2) % NSTAGE, (c + 2) << 6); CP_COMMIT(); }

        const uint32_t sA = sb + (uint32_t)(c % NSTAGE) * STAGE_SZ;
#pragma unroll
        for (int ks = 0; ks < 4; ks++) {
            const uint32_t offA = (uint32_t)(((ks * 2 + cpartA) << 4)) ^ xorv;
            const uint32_t offB = (uint32_t)(((ks * 2 + kpB) << 4)) ^ xorv;
            uint32_t a0[4], a1[4];
            LDSM4(a0, sA + ST_A + pA + offA);
            LDSM4(a1, sA + ST_A + pA + 2048 + offA);
#pragma unroll
            for (int jp = 0; jp < 4; jp++) {
                uint32_t bh4[4], bl4[4];
                const uint32_t boff = pB4 + (uint32_t)(jp * 2048) + offB;
                LDSM4(bh4, sA + ST_BH + boff);
                LDSM4(bl4, sA + ST_BL + boff);
                const int j0 = jp * 2, j1 = jp * 2 + 1;
                MMA_F16(acc[0][j0], a0, bh4[0], bh4[1]);
                MMA_F16(acc[1][j0], a1, bh4[0], bh4[1]);
                MMA_F16(acc[0][j1], a0, bh4[2], bh4[3]);
                MMA_F16(acc[1][j1], a1, bh4[2], bh4[3]);
                MMA_F16(acc[0][j0], a0, bl4[0], bl4[1]);
                MMA_F16(acc[1][j0], a1, bl4[0], bl4[1]);
                MMA_F16(acc[0][j1], a0, bl4[2], bl4[3]);
                MMA_F16(acc[1][j1], a1, bl4[2], bl4[3]);
            }
        }
    }

    // ---------------- epilogue ----------------
    const int qrow = lane >> 2;
    const int qcol = 2 * (lane & 3);
#pragma unroll
    for (int t = 0; t < 2; t++) {
#pragma unroll
        for (int j = 0; j < 8; j++) {
            const int colL = nb + j * 8 + qcol;
            const float b0 = bias_s[colL], b1 = bias_s[colL + 1];
#pragma unroll
            for (int h = 0; h < 2; h++) {
                const int row = gm + wm + t * 16 + h * 8 + qrow;
                float v0 = acc[t][j][h * 2 + 0] + b0;
                float v1 = acc[t][j][h * 2 + 1] + b1;
                if (Cf) {
                    *(float2*)(Cf + (size_t)row * ldc + gn + colL) = make_float2(v0, v1);
                } else {
                    v0 = fmaxf(v0, 0.0f); v1 = fmaxf(v1, 0.0f);
                    __half2 hv = __floats2half2_rn(v0, v1);
                    *(uint32_t*)(Ch + (size_t)row * ldc + gn + colL) =
                        *(uint32_t*)&hv;
                }
            }
        }
    }
}

// ---------------- RQS spline + logdet reduction ----------------
__device__ __forceinline__ float softplusf(float v) {
    return (v > 20.0f) ? v : log1pf(expf(v));
}

__global__ void k_spline(const float* __restrict__ x, const float* __restrict__ out,
                         float* __restrict__ y_out, float* __restrict__ ld_out) {
    const int b = blockIdx.x;
    const int i = threadIdx.x;

    __shared__ float srow[N_OUT];
    const float4* orow = (const float4*)(out + (size_t)b * N_OUT_P);
#pragma unroll
    for (int u = i; u < N_OUT / 4; u += N_IN) ((float4*)srow)[u] = orow[u];
    __syncthreads();

    const float* o = srow + i * OUT_MULT;
    const float xi = x[(size_t)b * N_IN + i];

    float uw[NB], uh[NB];
#pragma unroll
    for (int j = 0; j < NB; j++) {
        uw[j] = o[j]      * (1.0f / RQS_SCALE);
        uh[j] = o[NB + j] * (1.0f / RQS_SCALE);
    }
    float mw = uw[0], mh = uh[0];
#pragma unroll
    for (int j = 1; j < NB; j++) { mw = fmaxf(mw, uw[j]); mh = fmaxf(mh, uh[j]); }
    float ew[NB], eh[NB], sw = 0.0f, sh = 0.0f;
#pragma unroll
    for (int j = 0; j < NB; j++) {
        ew[j] = expf(uw[j] - mw); sw += ew[j];
        eh[j] = expf(uh[j] - mh); sh += eh[j];
    }
    const float rw = (1.0f - MIN_W * NB) / sw;
    const float rh = (1.0f - MIN_H * NB) / sh;

    float cw[NB + 1], ch[NB + 1];
    cw[0] = -TAIL; ch[0] = -TAIL;
    float accw = 0.0f, acch = 0.0f;
#pragma unroll
    for (int j = 0; j < NB; j++) {
        accw += MIN_W + rw * ew[j];
        acch += MIN_H + rh * eh[j];
        cw[j + 1] = 2.0f * TAIL * accw - TAIL;
        ch[j + 1] = 2.0f * TAIL * acch - TAIL;
    }
    cw[NB] = TAIL; ch[NB] = TAIL;

    float d[NB + 1];
    d[0] = 1.0f; d[NB] = 1.0f;
#pragma unroll
    for (int j = 1; j < NB; j++) d[j] = MIN_D + softplusf(o[2 * NB + j - 1]);

    const float xc = fminf(fmaxf(xi, -TAIL), TAIL);
    int idx = 0;
#pragma unroll
    for (int k = 1; k <= NB; k++) idx += (xc >= cw[k]) ? 1 : 0;
    idx = min(idx, NB - 1);

    const float in_cw = cw[idx];
    const float in_w  = cw[idx + 1] - cw[idx];
    const float in_ch = ch[idx];
    const float in_h  = ch[idx + 1] - ch[idx];
    const float delta = in_h / in_w;
    const float d0 = d[idx], d1 = d[idx + 1];

    const float theta = (xc - in_cw) / in_w;
    const float t1m   = theta * (1.0f - theta);
    const float denom = delta + (d0 + d1 - 2.0f * delta) * t1m;
    const float num   = in_h * (delta * theta * theta + d0 * t1m);
    float y  = in_ch + num / denom;
    float ld = 2.0f * logf(delta)
             + logf(d1 * theta * theta + 2.0f * delta * t1m + d0 * (1.0f - theta) * (1.0f - theta))
             - 2.0f * logf(denom);

    const bool inside = fabsf(xi) <= TAIL;
    y_out[(size_t)b * N_IN + i] = inside ? y : xi;
    float ldv = inside ? ld : 0.0f;

    __shared__ float warp_sums[4];
#pragma unroll
    for (int off = 16; off > 0; off >>= 1)
        ldv += __shfl_down_sync(0xFFFFFFFFu, ldv, off);
    if ((i & 31) == 0) warp_sums[i >> 5] = ldv;
    __syncthreads();
    if (i == 0)
        ld_out[b] = warp_sums[0] + warp_sums[1] + warp_sums[2] + warp_sums[3];
}

// ---------------- launch ----------------
extern "C" void kernel_launch(void* const* d_in, const int* in_sizes, int n_in,
                              void* d_out, int out_size) {
    const float* x      = (const float*)d_in[0];
    const float* context= (const float*)d_in[1];
    const float* ctx_w  = (const float*)d_in[2];
    const float* w0     = (const float*)d_in[3];
    const float* b0     = (const float*)d_in[4];
    const float* w1     = (const float*)d_in[5];
    const float* b1     = (const float*)d_in[6];
    const float* w2     = (const float*)d_in[7];
    const float* b2     = (const float*)d_in[8];

    __half *xc, *wch, *wcl, *w1h, *w1l, *w2h, *w2l, *h0, *h1;
    float *obuf, *b0p, *b1p;
    cudaGetSymbolAddress((void**)&xc,  g_xcat);
    cudaGetSymbolAddress((void**)&wch, g_wcat_hi); cudaGetSymbolAddress((void**)&wcl, g_wcat_lo);
    cudaGetSymbolAddress((void**)&w1h, g_w1_hi);   cudaGetSymbolAddress((void**)&w1l, g_w1_lo);
    cudaGetSymbolAddress((void**)&w2h, g_w2_hi);   cudaGetSymbolAddress((void**)&w2l, g_w2_lo);
    cudaGetSymbolAddress((void**)&h0,  g_h0);
    cudaGetSymbolAddress((void**)&h1,  g_h1);
    cudaGetSymbolAddress((void**)&obuf, g_out);
    cudaGetSymbolAddress((void**)&b0p, g_b0p);
    cudaGetSymbolAddress((void**)&b1p, g_b1p);

    cudaFuncSetAttribute(gemm_mma, cudaFuncAttributeMaxDynamicSharedMemorySize, GSMEM);

    const int TPB = 256;
    k_prep_xcat<<<(BATCH * KCAT + TPB - 1) / TPB, TPB>>>(x, context, xc);
    k_prep_wcat<<<(HDIM * KCAT + TPB - 1) / TPB, TPB>>>(ctx_w, w0, wch, wcl);
    k_prep_w1 <<<(HDIM * HDIM + TPB - 1) / TPB, TPB>>>(w1, w1h, w1l);
    k_prep_w2 <<<(N_OUT * HDIM + TPB - 1) / TPB, TPB>>>(w2, w2h, w2l);
    k_prep_bias<<<(HDIM + TPB - 1) / TPB, TPB>>>(b0, b1, b0p, b1p);

    // layer 1: triangular x-half (mode 0)
    gemm_mma<<<dim3(HDIM / 128, BATCH / 128), 256, GSMEM>>>(
        xc, wch, wcl, b0p, KCAT, HDIM, 0, h0, nullptr, HDIM);
    // layer 2: sorted->sorted triangular (mode 1)
    gemm_mma<<<dim3(HDIM / 128, BATCH / 128), 256, GSMEM>>>(
        h0, w1h, w1l, b1p, HDIM, HDIM, 1, h1, nullptr, HDIM);
    // layer 3: natural rows vs sorted cols (mode 2)
    gemm_mma<<<dim3(N_OUT / 128, BATCH / 128), 256, GSMEM>>>(
        h1, w2h, w2l, b2, HDIM, N_OUT, 2, nullptr, obuf, N_OUT_P);

    float* yout = (float*)d_out;
    float* ldout = (float*)d_out + (size_t)BATCH * N_IN;
    k_spline<<<BATCH, N_IN>>>(x, obuf, yout, ldout);
}

// round 10
// speedup vs baseline: 4.1824x; 1.3554x over previous
#include <cuda_runtime.h>
#include <cuda_fp16.h>
#include <math.h>
#include <stdint.h>

// ---------------- problem constants ----------------
#define BATCH   16384
#define N_IN    128
#define CTX     128
#define HDIM    1024
#define NB      8
#define OUT_MULT 23                  // 3*NB - 1
#define N_OUT   (N_IN * OUT_MULT)    // 2944 = 23 * 128 exactly
#define N_OUT_P 3072                 // obuf row padding
#define KCAT    (CTX + N_IN)         // 256
#define TAIL    3.0f
#define MIN_W   0.001f
#define MIN_H   0.001f
#define MIN_D   0.001f
#define RQS_SCALE 724.07734393502f   // sqrt(1024*1024/2)

// Pure fp16 scheme: C = f16(A) @ f16(B)^T, fp32 accumulate.
// Error: (a-f16(a))·b + a·(b-f16(b)) ~ 2^-12 RMS relative per layer.

// ---------------- scratch ----------------
__device__ __half g_xcat[(size_t)BATCH * KCAT];
__device__ __half g_wcat[(size_t)HDIM * KCAT];
__device__ __half g_w1[(size_t)HDIM * HDIM];
__device__ __half g_w2[(size_t)N_OUT * HDIM];
__device__ __half g_h0[(size_t)BATCH * HDIM];
__device__ __half g_h1[(size_t)BATCH * HDIM];
__device__ float  g_out[(size_t)BATCH * N_OUT_P];
__device__ float  g_b0p[HDIM];
__device__ float  g_b1p[HDIM];

// ---------------- degree-sorted hidden permutation (analytic) ----------------
__host__ __device__ __forceinline__ int sorted_res(int j) {
    return (j < 72) ? (j / 9) : (8 + (j - 72) / 8);
}
__host__ __device__ __forceinline__ int sorted_orig(int j) {
    int r, c;
    if (j < 72) { r = j / 9; c = j % 9; }
    else        { int u = j - 72; r = 8 + u / 8; c = u % 8; }
    return c * 127 + r;
}

// ---------------- baseline-PTX helpers (compute_103-safe) ----------------
__device__ __forceinline__ uint32_t smem_to_u32(const void* p) {
    uint32_t a;
    asm("{ .reg .u64 t; cvta.to.shared.u64 t, %1; cvt.u32.u64 %0, t; }" : "=r"(a) : "l"(p));
    return a;
}

#define CP_ASYNC16(saddr, gptr) \
    asm volatile("cp.async.cg.shared.global [%0], [%1], 16;" :: "r"(saddr), "l"(gptr) : "memory")
#define CP_COMMIT()   asm volatile("cp.async.commit_group;" ::: "memory")
#define CP_WAIT(n)    asm volatile("cp.async.wait_group %0;" :: "n"(n) : "memory")

#define LDSM4(R, addr) \
    asm volatile("ldmatrix.sync.aligned.m8n8.x4.shared.b16 {%0,%1,%2,%3}, [%4];" \
        : "=r"((R)[0]), "=r"((R)[1]), "=r"((R)[2]), "=r"((R)[3]) : "r"(addr))

#define MMA_F16(C, A, B0, B1) \
    asm volatile("mma.sync.aligned.m16n8k16.row.col.f32.f16.f16.f32 " \
        "{%0,%1,%2,%3}, {%4,%5,%6,%7}, {%8,%9}, {%0,%1,%2,%3};" \
        : "+f"((C)[0]), "+f"((C)[1]), "+f"((C)[2]), "+f"((C)[3]) \
        : "r"((A)[0]), "r"((A)[1]), "r"((A)[2]), "r"((A)[3]), "r"(B0), "r"(B1))

// ---------------- prep kernels ----------------
__global__ void k_prep_xcat(const float* __restrict__ x, const float* __restrict__ ctx,
                            __half* __restrict__ a) {
    int idx = blockIdx.x * blockDim.x + threadIdx.x;
    if (idx >= BATCH * KCAT) return;
    int b = idx >> 8, c = idx & 255;
    float v = (c < CTX) ? ctx[b * CTX + c] : x[b * N_IN + (c - CTX)];
    a[idx] = __float2half_rn(v);
}

__global__ void k_prep_wcat(const float* __restrict__ ctxw, const float* __restrict__ w0,
                            __half* __restrict__ w) {
    int idx = blockIdx.x * blockDim.x + threadIdx.x;
    if (idx >= HDIM * KCAT) return;
    int j = idx >> 8, c = idx & 255;
    int h = sorted_orig(j), r = sorted_res(j);
    float v;
    if (c < CTX) v = ctxw[h * CTX + c];
    else { int i = c - CTX; v = (r >= i) ? w0[h * N_IN + i] : 0.0f; }
    w[idx] = __float2half_rn(v);
}

__global__ void k_prep_w1(const float* __restrict__ w1, __half* __restrict__ w) {
    int idx = blockIdx.x * blockDim.x + threadIdx.x;
    if (idx >= HDIM * HDIM) return;
    int j = idx >> 10, j2 = idx & 1023;
    float v = (sorted_res(j) >= sorted_res(j2))
            ? w1[(size_t)sorted_orig(j) * HDIM + sorted_orig(j2)] : 0.0f;
    w[idx] = __float2half_rn(v);
}

__global__ void k_prep_w2(const float* __restrict__ w2, __half* __restrict__ w) {
    int idx = blockIdx.x * blockDim.x + threadIdx.x;
    if (idx >= N_OUT * HDIM) return;
    int o = idx >> 10, j = idx & 1023;
    float v = ((o / OUT_MULT) > sorted_res(j)) ? w2[(size_t)o * HDIM + sorted_orig(j)] : 0.0f;
    w[idx] = __float2half_rn(v);
}

__global__ void k_prep_bias(const float* __restrict__ b0, const float* __restrict__ b1,
                            float* __restrict__ b0p, float* __restrict__ b1p) {
    int j = blockIdx.x * blockDim.x + threadIdx.x;
    if (j >= HDIM) return;
    int h = sorted_orig(j);
    b0p[j] = b0[h];
    b1p[j] = b1[h];
}

// ---------------- pure fp16 GEMM, triangular K-skip, 3-stage ---------------
#define ST_A  0
#define ST_B  16384
#define STAGE_SZ 32768
#define NSTAGE 3
#define GSMEM (NSTAGE * STAGE_SZ + 1024)

__global__ __launch_bounds__(256, 1)
void gemm_mma(const __half* __restrict__ A, const __half* __restrict__ B,
              const float* __restrict__ bias, int K, int nvalid, int mode,
              __half* __restrict__ Ch, float* __restrict__ Cf, int ldc) {
    extern __shared__ char smem[];
    const uint32_t sb = smem_to_u32(smem);
    float* bias_s = (float*)(smem + NSTAGE * STAGE_SZ);

    const int tid = threadIdx.x;
    const int lane = tid & 31, wid = tid >> 5;
    const int gm = blockIdx.y * 128;
    // Descending-K launch order: largest-work N tiles first.
    const int gn = (gridDim.x - 1 - blockIdx.x) * 128;

    if (tid < 128) bias_s[tid] = (gn + tid < nvalid) ? bias[gn + tid] : 0.0f;

    // per-CTA effective K from the mask structure
    int keff = K;
    if (mode == 0) {
        int r = sorted_res(gn + 127);
        keff = CTX + r + 1;
    } else if (mode == 1) {
        int rp = sorted_res(gn + 127) + 1;
        keff = 8 * rp + min(rp, 8);
    } else if (mode == 2) {
        int q = min(gn + 127, N_OUT - 1) / OUT_MULT;
        keff = 8 * q + min(q, 8);
    }
    keff = min(K, (keff + 63) & ~63);

    int r_[4], c_[4]; uint32_t soff_[4];
#pragma unroll
    for (int i = 0; i < 4; i++) {
        int u = i * 256 + tid;
        r_[i] = u >> 3; c_[i] = u & 7;
        soff_[i] = (uint32_t)(r_[i] * 128 + ((c_[i] ^ (r_[i] & 7)) << 4));
    }

    const int wm = (wid & 3) * 32;
    const int nb = (wid >> 2) * 64;
    const int lr = lane & 7;
    const int gA = (lane >> 3) & 1;
    const int cpartA = (lane >> 4) & 1;
    const int kpB = (lane >> 3) & 1;
    const uint32_t xorv = (uint32_t)lr << 4;
    const uint32_t pA  = (uint32_t)((wm + gA * 8 + lr) * 128);
    const uint32_t pB4 = (uint32_t)((nb + ((lane >> 4) & 1) * 8 + lr) * 128);

    float acc[2][8][4];
#pragma unroll
    for (int t = 0; t < 2; t++)
#pragma unroll
        for (int j = 0; j < 8; j++)
#pragma unroll
            for (int q = 0; q < 4; q++) acc[t][j][q] = 0.0f;

    const int nch = keff >> 6;

    auto load_stage = [&](int s, int k0) {
        uint32_t base = sb + (uint32_t)s * STAGE_SZ;
#pragma unroll
        for (int i = 0; i < 4; i++) {
            size_t ga = (size_t)(gm + r_[i]) * K + k0 + c_[i] * 8;
            size_t gb = (size_t)(gn + r_[i]) * K + k0 + c_[i] * 8;
            CP_ASYNC16(base + ST_A + soff_[i], A + ga);
            CP_ASYNC16(base + ST_B + soff_[i], B + gb);
        }
    };

    load_stage(0, 0);
    CP_COMMIT();
    if (nch > 1) { load_stage(1, 64); CP_COMMIT(); }

    for (int c = 0; c < nch; c++) {
        // stages 0..min(c+1, nch-1) committed; need stage c -> allow 1 pending.
        if (c + 1 < nch) CP_WAIT(1); else CP_WAIT(0);
        __syncthreads();

        if (c + 2 < nch) { load_stage((c + 2) % NSTAGE, (c + 2) << 6); CP_COMMIT(); }

        const uint32_t sA = sb + (uint32_t)(c % NSTAGE) * STAGE_SZ;
#pragma unroll
        for (int ks = 0; ks < 4; ks++) {
            const uint32_t offA = (uint32_t)(((ks * 2 + cpartA) << 4)) ^ xorv;
            const uint32_t offB = (uint32_t)(((ks * 2 + kpB) << 4)) ^ xorv;
            uint32_t a0[4], a1[4];
            LDSM4(a0, sA + ST_A + pA + offA);
            LDSM4(a1, sA + ST_A + pA + 2048 + offA);
#pragma unroll
            for (int jp = 0; jp < 4; jp++) {
                uint32_t b4[4];
                LDSM4(b4, sA + ST_B + pB4 + (uint32_t)(jp * 2048) + offB);
                const int j0 = jp * 2, j1 = jp * 2 + 1;
                MMA_F16(acc[0][j0], a0, b4[0], b4[1]);
                MMA_F16(acc[1][j0], a1, b4[0], b4[1]);
                MMA_F16(acc[0][j1], a0, b4[2], b4[3]);
                MMA_F16(acc[1][j1], a1, b4[2], b4[3]);
            }
        }
    }

    // ---------------- epilogue ----------------
    const int qrow = lane >> 2;
    const int qcol = 2 * (lane & 3);
#pragma unroll
    for (int t = 0; t < 2; t++) {
#pragma unroll
        for (int j = 0; j < 8; j++) {
            const int colL = nb + j * 8 + qcol;
            const float b0 = bias_s[colL], b1 = bias_s[colL + 1];
#pragma unroll
            for (int h = 0; h < 2; h++) {
                const int row = gm + wm + t * 16 + h * 8 + qrow;
                float v0 = acc[t][j][h * 2 + 0] + b0;
                float v1 = acc[t][j][h * 2 + 1] + b1;
                if (Cf) {
                    *(float2*)(Cf + (size_t)row * ldc + gn + colL) = make_float2(v0, v1);
                } else {
                    v0 = fmaxf(v0, 0.0f); v1 = fmaxf(v1, 0.0f);
                    __half2 hv = __floats2half2_rn(v0, v1);
                    *(uint32_t*)(Ch + (size_t)row * ldc + gn + colL) = *(uint32_t*)&hv;
                }
            }
        }
    }
}

// ---------------- RQS spline + logdet reduction ----------------
__device__ __forceinline__ float softplusf(float v) {
    return (v > 20.0f) ? v : log1pf(expf(v));
}

__global__ void k_spline(const float* __restrict__ x, const float* __restrict__ out,
                         float* __restrict__ y_out, float* __restrict__ ld_out) {
    const int b = blockIdx.x;
    const int i = threadIdx.x;

    __shared__ float srow[N_OUT];
    const float4* orow = (const float4*)(out + (size_t)b * N_OUT_P);
#pragma unroll
    for (int u = i; u < N_OUT / 4; u += N_IN) ((float4*)srow)[u] = orow[u];
    __syncthreads();

    const float* o = srow + i * OUT_MULT;
    const float xi = x[(size_t)b * N_IN + i];

    float uw[NB], uh[NB];
#pragma unroll
    for (int j = 0; j < NB; j++) {
        uw[j] = o[j]      * (1.0f / RQS_SCALE);
        uh[j] = o[NB + j] * (1.0f / RQS_SCALE);
    }
    float mw = uw[0], mh = uh[0];
#pragma unroll
    for (int j = 1; j < NB; j++) { mw = fmaxf(mw, uw[j]); mh = fmaxf(mh, uh[j]); }
    float ew[NB], eh[NB], sw = 0.0f, sh = 0.0f;
#pragma unroll
    for (int j = 0; j < NB; j++) {
        ew[j] = expf(uw[j] - mw); sw += ew[j];
        eh[j] = expf(uh[j] - mh); sh += eh[j];
    }
    const float rw = (1.0f - MIN_W * NB) / sw;
    const float rh = (1.0f - MIN_H * NB) / sh;

    float cw[NB + 1], ch[NB + 1];
    cw[0] = -TAIL; ch[0] = -TAIL;
    float accw = 0.0f, acch = 0.0f;
#pragma unroll
    for (int j = 0; j < NB; j++) {
        accw += MIN_W + rw * ew[j];
        acch += MIN_H + rh * eh[j];
        cw[j + 1] = 2.0f * TAIL * accw - TAIL;
        ch[j + 1] = 2.0f * TAIL * acch - TAIL;
    }
    cw[NB] = TAIL; ch[NB] = TAIL;

    float d[NB + 1];
    d[0] = 1.0f; d[NB] = 1.0f;
#pragma unroll
    for (int j = 1; j < NB; j++) d[j] = MIN_D + softplusf(o[2 * NB + j - 1]);

    const float xc = fminf(fmaxf(xi, -TAIL), TAIL);
    int idx = 0;
#pragma unroll
    for (int k = 1; k <= NB; k++) idx += (xc >= cw[k]) ? 1 : 0;
    idx = min(idx, NB - 1);

    const float in_cw = cw[idx];
    const float in_w  = cw[idx + 1] - cw[idx];
    const float in_ch = ch[idx];
    const float in_h  = ch[idx + 1] - ch[idx];
    const float delta = in_h / in_w;
    const float d0 = d[idx], d1 = d[idx + 1];

    const float theta = (xc - in_cw) / in_w;
    const float t1m   = theta * (1.0f - theta);
    const float denom = delta + (d0 + d1 - 2.0f * delta) * t1m;
    const float num   = in_h * (delta * theta * theta + d0 * t1m);
    float y  = in_ch + num / denom;
    float ld = 2.0f * logf(delta)
             + logf(d1 * theta * theta + 2.0f * delta * t1m + d0 * (1.0f - theta) * (1.0f - theta))
             - 2.0f * logf(denom);

    const bool inside = fabsf(xi) <= TAIL;
    y_out[(size_t)b * N_IN + i] = inside ? y : xi;
    float ldv = inside ? ld : 0.0f;

    __shared__ float warp_sums[4];
#pragma unroll
    for (int off = 16; off > 0; off >>= 1)
        ldv += __shfl_down_sync(0xFFFFFFFFu, ldv, off);
    if ((i & 31) == 0) warp_sums[i >> 5] = ldv;
    __syncthreads();
    if (i == 0)
        ld_out[b] = warp_sums[0] + warp_sums[1] + warp_sums[2] + warp_sums[3];
}

// ---------------- launch ----------------
extern "C" void kernel_launch(void* const* d_in, const int* in_sizes, int n_in,
                              void* d_out, int out_size) {
    const float* x      = (const float*)d_in[0];
    const float* context= (const float*)d_in[1];
    const float* ctx_w  = (const float*)d_in[2];
    const float* w0     = (const float*)d_in[3];
    const float* b0     = (const float*)d_in[4];
    const float* w1     = (const float*)d_in[5];
    const float* b1     = (const float*)d_in[6];
    const float* w2     = (const float*)d_in[7];
    const float* b2     = (const float*)d_in[8];

    __half *xc, *wc, *w1p, *w2p, *h0, *h1;
    float *obuf, *b0p, *b1p;
    cudaGetSymbolAddress((void**)&xc,  g_xcat);
    cudaGetSymbolAddress((void**)&wc,  g_wcat);
    cudaGetSymbolAddress((void**)&w1p, g_w1);
    cudaGetSymbolAddress((void**)&w2p, g_w2);
    cudaGetSymbolAddress((void**)&h0,  g_h0);
    cudaGetSymbolAddress((void**)&h1,  g_h1);
    cudaGetSymbolAddress((void**)&obuf, g_out);
    cudaGetSymbolAddress((void**)&b0p, g_b0p);
    cudaGetSymbolAddress((void**)&b1p, g_b1p);

    cudaFuncSetAttribute(gemm_mma, cudaFuncAttributeMaxDynamicSharedMemorySize, GSMEM);

    const int TPB = 256;
    k_prep_xcat<<<(BATCH * KCAT + TPB - 1) / TPB, TPB>>>(x, context, xc);
    k_prep_wcat<<<(HDIM * KCAT + TPB - 1) / TPB, TPB>>>(ctx_w, w0, wc);
    k_prep_w1 <<<(HDIM * HDIM + TPB - 1) / TPB, TPB>>>(w1, w1p);
    k_prep_w2 <<<(N_OUT * HDIM + TPB - 1) / TPB, TPB>>>(w2, w2p);
    k_prep_bias<<<(HDIM + TPB - 1) / TPB, TPB>>>(b0, b1, b0p, b1p);

    // layer 1: triangular x-half (mode 0)
    gemm_mma<<<dim3(HDIM / 128, BATCH / 128), 256, GSMEM>>>(
        xc, wc, b0p, KCAT, HDIM, 0, h0, nullptr, HDIM);
    // layer 2: sorted->sorted triangular (mode 1)
    gemm_mma<<<dim3(HDIM / 128, BATCH / 128), 256, GSMEM>>>(
        h0, w1p, b1p, HDIM, HDIM, 1, h1, nullptr, HDIM);
    // layer 3: natural rows vs sorted cols (mode 2)
    gemm_mma<<<dim3(N_OUT / 128, BATCH / 128), 256, GSMEM>>>(
        h1, w2p, b2, HDIM, N_OUT, 2, nullptr, obuf, N_OUT_P);

    float* yout = (float*)d_out;
    float* ldout = (float*)d_out + (size_t)BATCH * N_IN;
    k_spline<<<BATCH, N_IN>>>(x, obuf, yout, ldout);
}

// round 12
// speedup vs baseline: 4.9934x; 1.1939x over previous
#include <cuda_runtime.h>
#include <cuda_fp16.h>
#include <math.h>
#include <stdint.h>

// ---------------- problem constants ----------------
#define BATCH   16384
#define N_IN    128
#define CTX     128
#define HDIM    1024
#define NB      8
#define OUT_MULT 23                  // 3*NB - 1
#define N_OUT   (N_IN * OUT_MULT)    // 2944 = 23 * 128 exactly
#define N_OUT_P 3072                 // obuf row padding
#define KCAT    (CTX + N_IN)         // 256
#define TAIL    3.0f
#define MIN_W   0.001f
#define MIN_H   0.001f
#define MIN_D   0.001f
#define RQS_SCALE 724.07734393502f   // sqrt(1024*1024/2)

// Pure fp16 scheme: C = f16(A) @ f16(B)^T, fp32 accumulate.

// ---------------- scratch ----------------
__device__ __half g_xcat[(size_t)BATCH * KCAT];
__device__ __half g_wcat[(size_t)HDIM * KCAT];
__device__ __half g_w1[(size_t)HDIM * HDIM];
__device__ __half g_w2[(size_t)N_OUT * HDIM];
__device__ __half g_h0[(size_t)BATCH * HDIM];
__device__ __half g_h1[(size_t)BATCH * HDIM];
__device__ float  g_out[(size_t)BATCH * N_OUT_P];
__device__ float  g_b0p[HDIM];
__device__ float  g_b1p[HDIM];

// ---------------- degree-sorted hidden permutation (analytic) ----------------
__host__ __device__ __forceinline__ int sorted_res(int j) {
    return (j < 72) ? (j / 9) : (8 + (j - 72) / 8);
}
__host__ __device__ __forceinline__ int sorted_orig(int j) {
    int r, c;
    if (j < 72) { r = j / 9; c = j % 9; }
    else        { int u = j - 72; r = 8 + u / 8; c = u % 8; }
    return c * 127 + r;
}

// ---------------- baseline-PTX helpers (compute_103-safe) ----------------
__device__ __forceinline__ uint32_t smem_to_u32(const void* p) {
    uint32_t a;
    asm("{ .reg .u64 t; cvta.to.shared.u64 t, %1; cvt.u32.u64 %0, t; }" : "=r"(a) : "l"(p));
    return a;
}

#define CP_ASYNC16(saddr, gptr) \
    asm volatile("cp.async.cg.shared.global [%0], [%1], 16;" :: "r"(saddr), "l"(gptr) : "memory")
#define CP_COMMIT()   asm volatile("cp.async.commit_group;" ::: "memory")
#define CP_WAIT(n)    asm volatile("cp.async.wait_group %0;" :: "n"(n) : "memory")

#define LDSM4(R, addr) \
    asm volatile("ldmatrix.sync.aligned.m8n8.x4.shared.b16 {%0,%1,%2,%3}, [%4];" \
        : "=r"((R)[0]), "=r"((R)[1]), "=r"((R)[2]), "=r"((R)[3]) : "r"(addr))

#define MMA_F16(C, A, B0, B1) \
    asm volatile("mma.sync.aligned.m16n8k16.row.col.f32.f16.f16.f32 " \
        "{%0,%1,%2,%3}, {%4,%5,%6,%7}, {%8,%9}, {%0,%1,%2,%3};" \
        : "+f"((C)[0]), "+f"((C)[1]), "+f"((C)[2]), "+f"((C)[3]) \
        : "r"((A)[0]), "r"((A)[1]), "r"((A)[2]), "r"((A)[3]), "r"(B0), "r"(B1))

// ---------------- prep kernels ----------------
__global__ void k_prep_xcat(const float* __restrict__ x, const float* __restrict__ ctx,
                            __half* __restrict__ a) {
    int idx = blockIdx.x * blockDim.x + threadIdx.x;
    if (idx >= BATCH * KCAT) return;
    int b = idx >> 8, c = idx & 255;
    float v = (c < CTX) ? ctx[b * CTX + c] : x[b * N_IN + (c - CTX)];
    a[idx] = __float2half_rn(v);
}

__global__ void k_prep_wcat(const float* __restrict__ ctxw, const float* __restrict__ w0,
                            __half* __restrict__ w) {
    int idx = blockIdx.x * blockDim.x + threadIdx.x;
    if (idx >= HDIM * KCAT) return;
    int j = idx >> 8, c = idx & 255;
    int h = sorted_orig(j), r = sorted_res(j);
    float v;
    if (c < CTX) v = ctxw[h * CTX + c];
    else { int i = c - CTX; v = (r >= i) ? w0[h * N_IN + i] : 0.0f; }
    w[idx] = __float2half_rn(v);
}

__global__ void k_prep_w1(const float* __restrict__ w1, __half* __restrict__ w) {
    int idx = blockIdx.x * blockDim.x + threadIdx.x;
    if (idx >= HDIM * HDIM) return;
    int j = idx >> 10, j2 = idx & 1023;
    float v = (sorted_res(j) >= sorted_res(j2))
            ? w1[(size_t)sorted_orig(j) * HDIM + sorted_orig(j2)] : 0.0f;
    w[idx] = __float2half_rn(v);
}

__global__ void k_prep_w2(const float* __restrict__ w2, __half* __restrict__ w) {
    int idx = blockIdx.x * blockDim.x + threadIdx.x;
    if (idx >= N_OUT * HDIM) return;
    int o = idx >> 10, j = idx & 1023;
    float v = ((o / OUT_MULT) > sorted_res(j)) ? w2[(size_t)o * HDIM + sorted_orig(j)] : 0.0f;
    w[idx] = __float2half_rn(v);
}

__global__ void k_prep_bias(const float* __restrict__ b0, const float* __restrict__ b1,
                            float* __restrict__ b0p, float* __restrict__ b1p) {
    int j = blockIdx.x * blockDim.x + threadIdx.x;
    if (j >= HDIM) return;
    int h = sorted_orig(j);
    b0p[j] = b0[h];
    b1p[j] = b1[h];
}

// ---------------- pure fp16 GEMM, triangular K-skip, 3-stage, occ=2 --------
#define ST_A  0
#define ST_B  16384
#define STAGE_SZ 32768
#define NSTAGE 3
#define GSMEM (NSTAGE * STAGE_SZ + 1024)

__global__ __launch_bounds__(256, 2)
void gemm_mma(const __half* __restrict__ A, const __half* __restrict__ B,
              const float* __restrict__ bias, int K, int nvalid, int mode,
              __half* __restrict__ Ch, float* __restrict__ Cf, int ldc) {
    extern __shared__ char smem[];
    const uint32_t sb = smem_to_u32(smem);
    float* bias_s = (float*)(smem + NSTAGE * STAGE_SZ);

    const int tid = threadIdx.x;
    const int lane = tid & 31, wid = tid >> 5;
    const int gm = blockIdx.y * 128;
    // Descending-K launch order: largest-work N tiles first.
    const int gn = (gridDim.x - 1 - blockIdx.x) * 128;

    if (tid < 128) bias_s[tid] = (gn + tid < nvalid) ? bias[gn + tid] : 0.0f;

    // per-CTA effective K from the mask structure
    int keff = K;
    if (mode == 0) {
        int r = sorted_res(gn + 127);
        keff = CTX + r + 1;
    } else if (mode == 1) {
        int rp = sorted_res(gn + 127) + 1;
        keff = 8 * rp + min(rp, 8);
    } else if (mode == 2) {
        int q = min(gn + 127, N_OUT - 1) / OUT_MULT;
        keff = 8 * q + min(q, 8);
    }
    keff = min(K, (keff + 63) & ~63);

    int r_[4], c_[4]; uint32_t soff_[4];
#pragma unroll
    for (int i = 0; i < 4; i++) {
        int u = i * 256 + tid;
        r_[i] = u >> 3; c_[i] = u & 7;
        soff_[i] = (uint32_t)(r_[i] * 128 + ((c_[i] ^ (r_[i] & 7)) << 4));
    }

    const int wm = (wid & 3) * 32;
    const int nb = (wid >> 2) * 64;
    const int lr = lane & 7;
    const int gA = (lane >> 3) & 1;
    const int cpartA = (lane >> 4) & 1;
    const int kpB = (lane >> 3) & 1;
    const uint32_t xorv = (uint32_t)lr << 4;
    const uint32_t pA  = (uint32_t)((wm + gA * 8 + lr) * 128);
    const uint32_t pB4 = (uint32_t)((nb + ((lane >> 4) & 1) * 8 + lr) * 128);

    float acc[2][8][4];
#pragma unroll
    for (int t = 0; t < 2; t++)
#pragma unroll
        for (int j = 0; j < 8; j++)
#pragma unroll
            for (int q = 0; q < 4; q++) acc[t][j][q] = 0.0f;

    const int nch = keff >> 6;

    auto load_stage = [&](int s, int k0) {
        uint32_t base = sb + (uint32_t)s * STAGE_SZ;
#pragma unroll
        for (int i = 0; i < 4; i++) {
            size_t ga = (size_t)(gm + r_[i]) * K + k0 + c_[i] * 8;
            size_t gb = (size_t)(gn + r_[i]) * K + k0 + c_[i] * 8;
            CP_ASYNC16(base + ST_A + soff_[i], A + ga);
            CP_ASYNC16(base + ST_B + soff_[i], B + gb);
        }
    };

    load_stage(0, 0);
    CP_COMMIT();
    if (nch > 1) { load_stage(1, 64); CP_COMMIT(); }

    for (int c = 0; c < nch; c++) {
        // stages 0..min(c+1, nch-1) committed; need stage c -> allow 1 pending.
        if (c + 1 < nch) CP_WAIT(1); else CP_WAIT(0);
        __syncthreads();

        if (c + 2 < nch) { load_stage((c + 2) % NSTAGE, (c + 2) << 6); CP_COMMIT(); }

        const uint32_t sA = sb + (uint32_t)(c % NSTAGE) * STAGE_SZ;
#pragma unroll
        for (int ks = 0; ks < 4; ks++) {
            const uint32_t offA = (uint32_t)(((ks * 2 + cpartA) << 4)) ^ xorv;
            const uint32_t offB = (uint32_t)(((ks * 2 + kpB) << 4)) ^ xorv;
            uint32_t a0[4], a1[4];
            LDSM4(a0, sA + ST_A + pA + offA);
            LDSM4(a1, sA + ST_A + pA + 2048 + offA);
#pragma unroll
            for (int jp = 0; jp < 4; jp++) {
                uint32_t b4[4];
                LDSM4(b4, sA + ST_B + pB4 + (uint32_t)(jp * 2048) + offB);
                const int j0 = jp * 2, j1 = jp * 2 + 1;
                MMA_F16(acc[0][j0], a0, b4[0], b4[1]);
                MMA_F16(acc[1][j0], a1, b4[0], b4[1]);
                MMA_F16(acc[0][j1], a0, b4[2], b4[3]);
                MMA_F16(acc[1][j1], a1, b4[2], b4[3]);
            }
        }
    }

    // ---------------- epilogue ----------------
    const int qrow = lane >> 2;
    const int qcol = 2 * (lane & 3);
#pragma unroll
    for (int t = 0; t < 2; t++) {
#pragma unroll
        for (int j = 0; j < 8; j++) {
            const int colL = nb + j * 8 + qcol;
            const float b0 = bias_s[colL], b1 = bias_s[colL + 1];
#pragma unroll
            for (int h = 0; h < 2; h++) {
                const int row = gm + wm + t * 16 + h * 8 + qrow;
                float v0 = acc[t][j][h * 2 + 0] + b0;
                float v1 = acc[t][j][h * 2 + 1] + b1;
                if (Cf) {
                    *(float2*)(Cf + (size_t)row * ldc + gn + colL) = make_float2(v0, v1);
                } else {
                    v0 = fmaxf(v0, 0.0f); v1 = fmaxf(v1, 0.0f);
                    __half2 hv = __floats2half2_rn(v0, v1);
                    *(uint32_t*)(Ch + (size_t)row * ldc + gn + colL) = *(uint32_t*)&hv;
                }
            }
        }
    }
}

// ---------------- RQS spline + logdet reduction (2 rows per block) ---------
__device__ __forceinline__ float softplusf(float v) {
    return (v > 20.0f) ? v : log1pf(expf(v));
}

__global__ __launch_bounds__(256)
void k_spline(const float* __restrict__ x, const float* __restrict__ out,
              float* __restrict__ y_out, float* __restrict__ ld_out) {
    const int half = threadIdx.x >> 7;            // 0 or 1: which row
    const int b = blockIdx.x * 2 + half;
    const int i = threadIdx.x & 127;

    __shared__ float srow[2][N_OUT];
    const float4* orow = (const float4*)(out + (size_t)b * N_OUT_P);
#pragma unroll
    for (int u = i; u < N_OUT / 4; u += N_IN) ((float4*)srow[half])[u] = orow[u];
    __syncthreads();

    const float* o = srow[half] + i * OUT_MULT;
    const float xi = x[(size_t)b * N_IN + i];

    float uw[NB], uh[NB];
#pragma unroll
    for (int j = 0; j < NB; j++) {
        uw[j] = o[j]      * (1.0f / RQS_SCALE);
        uh[j] = o[NB + j] * (1.0f / RQS_SCALE);
    }
    float mw = uw[0], mh = uh[0];
#pragma unroll
    for (int j = 1; j < NB; j++) { mw = fmaxf(mw, uw[j]); mh = fmaxf(mh, uh[j]); }
    float ew[NB], eh[NB], sw = 0.0f, sh = 0.0f;
#pragma unroll
    for (int j = 0; j < NB; j++) {
        ew[j] = expf(uw[j] - mw); sw += ew[j];
        eh[j] = expf(uh[j] - mh); sh += eh[j];
    }
    const float rw = (1.0f - MIN_W * NB) / sw;
    const float rh = (1.0f - MIN_H * NB) / sh;

    float cw[NB + 1], ch[NB + 1];
    cw[0] = -TAIL; ch[0] = -TAIL;
    float accw = 0.0f, acch = 0.0f;
#pragma unroll
    for (int j = 0; j < NB; j++) {
        accw += MIN_W + rw * ew[j];
        acch += MIN_H + rh * eh[j];
        cw[j + 1] = 2.0f * TAIL * accw - TAIL;
        ch[j + 1] = 2.0f * TAIL * acch - TAIL;
    }
    cw[NB] = TAIL; ch[NB] = TAIL;

    float d[NB + 1];
    d[0] = 1.0f; d[NB] = 1.0f;
#pragma unroll
    for (int j = 1; j < NB; j++) d[j] = MIN_D + softplusf(o[2 * NB + j - 1]);

    const float xc = fminf(fmaxf(xi, -TAIL), TAIL);
    int idx = 0;
#pragma unroll
    for (int k = 1; k <= NB; k++) idx += (xc >= cw[k]) ? 1 : 0;
    idx = min(idx, NB - 1);

    const float in_cw = cw[idx];
    const float in_w  = cw[idx + 1] - cw[idx];
    const float in_ch = ch[idx];
    const float in_h  = ch[idx + 1] - ch[idx];
    const float delta = in_h / in_w;
    const float d0 = d[idx], d1 = d[idx + 1];

    const float theta = (xc - in_cw) / in_w;
    const float t1m   = theta * (1.0f - theta);
    const float denom = delta + (d0 + d1 - 2.0f * delta) * t1m;
    const float num   = in_h * (delta * theta * theta + d0 * t1m);
    float y  = in_ch + num / denom;
    float ld = 2.0f * logf(delta)
             + logf(d1 * theta * theta + 2.0f * delta * t1m + d0 * (1.0f - theta) * (1.0f - theta))
             - 2.0f * logf(denom);

    const bool inside = fabsf(xi) <= TAIL;
    y_out[(size_t)b * N_IN + i] = inside ? y : xi;
    float ldv = inside ? ld : 0.0f;

    __shared__ float warp_sums[8];
#pragma unroll
    for (int off = 16; off > 0; off >>= 1)
        ldv += __shfl_down_sync(0xFFFFFFFFu, ldv, off);
    if ((threadIdx.x & 31) == 0) warp_sums[threadIdx.x >> 5] = ldv;
    __syncthreads();
    if ((threadIdx.x & 127) == 0) {
        int base = half * 4;
        ld_out[b] = warp_sums[base] + warp_sums[base + 1]
                  + warp_sums[base + 2] + warp_sums[base + 3];
    }
}

// ---------------- launch ----------------
extern "C" void kernel_launch(void* const* d_in, const int* in_sizes, int n_in,
                              void* d_out, int out_size) {
    const float* x      = (const float*)d_in[0];
    const float* context= (const float*)d_in[1];
    const float* ctx_w  = (const float*)d_in[2];
    const float* w0     = (const float*)d_in[3];
    const float* b0     = (const float*)d_in[4];
    const float* w1     = (const float*)d_in[5];
    const float* b1     = (const float*)d_in[6];
    const float* w2     = (const float*)d_in[7];
    const float* b2     = (const float*)d_in[8];

    __half *xc, *wc, *w1p, *w2p, *h0, *h1;
    float *obuf, *b0p, *b1p;
    cudaGetSymbolAddress((void**)&xc,  g_xcat);
    cudaGetSymbolAddress((void**)&wc,  g_wcat);
    cudaGetSymbolAddress((void**)&w1p, g_w1);
    cudaGetSymbolAddress((void**)&w2p, g_w2);
    cudaGetSymbolAddress((void**)&h0,  g_h0);
    cudaGetSymbolAddress((void**)&h1,  g_h1);
    cudaGetSymbolAddress((void**)&obuf, g_out);
    cudaGetSymbolAddress((void**)&b0p, g_b0p);
    cudaGetSymbolAddress((void**)&b1p, g_b1p);

    cudaFuncSetAttribute(gemm_mma, cudaFuncAttributeMaxDynamicSharedMemorySize, GSMEM);

    const int TPB = 256;
    k_prep_xcat<<<(BATCH * KCAT + TPB - 1) / TPB, TPB>>>(x, context, xc);
    k_prep_wcat<<<(HDIM * KCAT + TPB - 1) / TPB, TPB>>>(ctx_w, w0, wc);
    k_prep_w1 <<<(HDIM * HDIM + TPB - 1) / TPB, TPB>>>(w1, w1p);
    k_prep_w2 <<<(N_OUT * HDIM + TPB - 1) / TPB, TPB>>>(w2, w2p);
    k_prep_bias<<<(HDIM + TPB - 1) / TPB, TPB>>>(b0, b1, b0p, b1p);

    // layer 1: triangular x-half (mode 0)
    gemm_mma<<<dim3(HDIM / 128, BATCH / 128), 256, GSMEM>>>(
        xc, wc, b0p, KCAT, HDIM, 0, h0, nullptr, HDIM);
    // layer 2: sorted->sorted triangular (mode 1)
    gemm_mma<<<dim3(HDIM / 128, BATCH / 128), 256, GSMEM>>>(
        h0, w1p, b1p, HDIM, HDIM, 1, h1, nullptr, HDIM);
    // layer 3: natural rows vs sorted cols (mode 2)
    gemm_mma<<<dim3(N_OUT / 128, BATCH / 128), 256, GSMEM>>>(
        h1, w2p, b2, HDIM, N_OUT, 2, nullptr, obuf, N_OUT_P);

    float* yout = (float*)d_out;
    float* ldout = (float*)d_out + (size_t)BATCH * N_IN;
    k_spline<<<BATCH / 2, 256>>>(x, obuf, yout, ldout);
}